// round 12
// baseline (speedup 1.0000x reference)
#include <cuda_runtime.h>
#include <math.h>

// Problem constants (fixed by the reference: B=8, N=8192, D=3)
#define BATCH   8
#define NPTS    8192
#define TOTAL   (BATCH * NPTS)        // 65536
#define G       32                    // cells per axis
#define NC      (G * G * G)           // 32768 cells per batch (2^15)
#define GRID_LO (-4.5f)
#define CELL_H  (0.28125f)            // 9.0 / 32
#define INV_H   (1.0f / CELL_H)
#define F_INF   __int_as_float(0x7f800000)
#define TPTS    128                   // ori points per tile
#define NTILE   (NPTS / TPTS)         // 64 tiles per batch

// Static scratch (no device allocation allowed).
__device__ int    g_cnt_ori[BATCH * NC];
__device__ int    g_off_ori[BATCH * NC];
__device__ int    g_cur_ori[BATCH * NC];
__device__ int    g_cnt_adv[BATCH * NC];
__device__ int    g_off_adv[BATCH * NC];
__device__ int    g_cur_adv[BATCH * NC];
__device__ float4 g_sorted_ori[TOTAL];   // (x, y, z, 0.5*||o||^2), Morton-cell order
__device__ float4 g_sorted_adv[TOTAL];   // (x, y, z, ||a||^2),    Morton-cell order
__device__ int    g_adv_meta[TOTAL];     // (mcell << 13) | orig-index-in-batch
__device__ float4 g_tlo[BATCH * NTILE];  // tile AABB lows
__device__ float4 g_thi[BATCH * NTILE];  // tile AABB highs
__device__ float  g_res[TOTAL];          // per-query nearest dist^2, original order

__device__ __forceinline__ int cell1(float v) {
    int c = (int)floorf((v - GRID_LO) * INV_H);
    return min(G - 1, max(0, c));
}
// Spread 5 bits -> every 3rd bit (standard Morton helper).
__device__ __forceinline__ unsigned spread3(unsigned x) {
    x &= 0x3FF;
    x = (x | (x << 16)) & 0x030000FF;
    x = (x | (x << 8))  & 0x0300F00F;
    x = (x | (x << 4))  & 0x030C30C3;
    x = (x | (x << 2))  & 0x09249249;
    return x;
}
__device__ __forceinline__ int morton3(int cx, int cy, int cz) {
    return (int)(spread3(cx) | (spread3(cy) << 1) | (spread3(cz) << 2));
}
__device__ __forceinline__ int mcell_of(const float* p) {
    return morton3(cell1(p[0]), cell1(p[1]), cell1(p[2]));
}

// ---------------------------------------------------------------- zero
__global__ void k_zero() {
    int i = blockIdx.x * blockDim.x + threadIdx.x;
    int stride = gridDim.x * blockDim.x;
    for (; i < BATCH * NC; i += stride) { g_cnt_ori[i] = 0; g_cnt_adv[i] = 0; }
}

// ---------------------------------------------------------------- count (Morton bins)
__global__ void k_count(const float* __restrict__ ori, const float* __restrict__ adv) {
    int t = blockIdx.x * blockDim.x + threadIdx.x;
    bool is_ori = t < TOTAL;
    int idx = is_ori ? t : t - TOTAL;
    int b = idx >> 13, i = idx & (NPTS - 1);
    const float* p = (is_ori ? ori : adv) + ((size_t)b * NPTS + i) * 3;
    int mc = mcell_of(p);
    atomicAdd((is_ori ? g_cnt_ori : g_cnt_adv) + b * NC + mc, 1);
}

// ---------------------------------------------------------------- scan (batch-local offsets)
// Blocks 0..7: ori batches. Blocks 8..15: adv batches. 1024 threads, CH=32.
__global__ void k_scan() {
    __shared__ int s[1024];
    int kind = blockIdx.x >> 3, b = blockIdx.x & 7, t = threadIdx.x;
    int* cnt = (kind ? g_cnt_adv : g_cnt_ori) + b * NC;
    int* off = (kind ? g_off_adv : g_off_ori) + b * NC;
    int* cur = (kind ? g_cur_adv : g_cur_ori) + b * NC;
    const int CH = NC / 1024;   // 32
    int base = t * CH;
    int local = 0;
#pragma unroll
    for (int j = 0; j < CH; j++) local += cnt[base + j];
    s[t] = local;
    __syncthreads();
    for (int d = 1; d < 1024; d <<= 1) {
        int v = (t >= d) ? s[t - d] : 0;
        __syncthreads();
        s[t] += v;
        __syncthreads();
    }
    int run = s[t] - local;
    for (int j = 0; j < CH; j++) {
        off[base + j] = run;
        cur[base + j] = run;
        run += cnt[base + j];
    }
}

// ---------------------------------------------------------------- scatter (Morton order)
__global__ void k_scatter(const float* __restrict__ ori, const float* __restrict__ adv) {
    int t = blockIdx.x * blockDim.x + threadIdx.x;
    bool is_ori = t < TOTAL;
    int idx = is_ori ? t : t - TOTAL;
    int b = idx >> 13, i = idx & (NPTS - 1);
    const float* p = (is_ori ? ori : adv) + ((size_t)b * NPTS + i) * 3;
    float x = p[0], y = p[1], z = p[2];
    int mc = morton3(cell1(x), cell1(y), cell1(z));
    if (is_ori) {
        int pos = atomicAdd(&g_cur_ori[b * NC + mc], 1);   // batch-local
        g_sorted_ori[b * NPTS + pos] = make_float4(x, y, z, 0.5f * (x * x + y * y + z * z));
    } else {
        int pos = atomicAdd(&g_cur_adv[b * NC + mc], 1);
        g_sorted_adv[b * NPTS + pos] = make_float4(x, y, z, x * x + y * y + z * z);
        g_adv_meta[b * NPTS + pos] = (mc << 13) | i;
    }
}

// ---------------------------------------------------------------- tile AABBs
// Warp per tile (512 tiles): lanes load 4 points each, shfl min/max reduce.
__global__ __launch_bounds__(256) void k_aabb() {
    const int tglob = blockIdx.x * 8 + (threadIdx.x >> 5);  // 0..511
    const int lane = threadIdx.x & 31;
    float lx = F_INF, ly = F_INF, lz = F_INF;
    float hx = -F_INF, hy = -F_INF, hz = -F_INF;
#pragma unroll
    for (int k = 0; k < 4; k++) {
        float4 p = g_sorted_ori[tglob * TPTS + k * 32 + lane];
        lx = fminf(lx, p.x); ly = fminf(ly, p.y); lz = fminf(lz, p.z);
        hx = fmaxf(hx, p.x); hy = fmaxf(hy, p.y); hz = fmaxf(hz, p.z);
    }
#pragma unroll
    for (int s = 16; s > 0; s >>= 1) {
        lx = fminf(lx, __shfl_xor_sync(0xffffffffu, lx, s));
        ly = fminf(ly, __shfl_xor_sync(0xffffffffu, ly, s));
        lz = fminf(lz, __shfl_xor_sync(0xffffffffu, lz, s));
        hx = fmaxf(hx, __shfl_xor_sync(0xffffffffu, hx, s));
        hy = fmaxf(hy, __shfl_xor_sync(0xffffffffu, hy, s));
        hz = fmaxf(hz, __shfl_xor_sync(0xffffffffu, hz, s));
    }
    if (lane == 0) {
        g_tlo[tglob] = make_float4(lx, ly, lz, 0.f);
        g_thi[tglob] = make_float4(hx, hy, hz, 0.f);
    }
}

// ---------------------------------------------------------------- query
// Thread = one sorted query. Warp queries are co-located (Morton-sorted adv).
// Evaluate the query's home tile first (warp-uniform), then sweep all 64 tiles
// with an exact AABB lower-bound skip (__all_sync). mn tracked in v-space:
// d^2 = ra + 2*v; skip tile iff boxdist^2 >= ra + 2*mn for EVERY lane.
__global__ __launch_bounds__(128) void k_query(int dummy) {
    const int slot = blockIdx.x * 128 + threadIdx.x;   // 0..TOTAL-1
    const int b = slot >> 13;                          // blocks never straddle batches
    const float4 q = g_sorted_adv[slot];
    const int meta = g_adv_meta[slot];
    const int orig = meta & (NPTS - 1);
    const int mc = meta >> 13;
    const float qx = q.x, qy = q.y, qz = q.z, ra = q.w;
    const float nqx = -qx, nqy = -qy, nqz = -qz;
    const float4* __restrict__ so = g_sorted_ori + b * NPTS;

    // Home tile: tile containing the start of this query's Morton cell run.
    int t0 = min(g_off_ori[b * NC + mc] >> 7, NTILE - 1);
    t0 = __shfl_sync(0xffffffffu, t0, 0);              // warp-uniform

    float mn = F_INF;
    {   // evaluate home tile (seeds a finite min for the bound tests)
        const float4* __restrict__ tp = so + t0 * TPTS;
#pragma unroll 4
        for (int j = 0; j < TPTS; j++) {
            const float4 o = __ldg(tp + j);
            const float v = fmaf(nqx, o.x, fmaf(nqy, o.y, fmaf(nqz, o.z, o.w)));
            mn = fminf(mn, v);
        }
    }

    for (int t = 0; t < NTILE; t++) {
        if (t == t0) continue;
        const float4 lo = g_tlo[b * NTILE + t];
        const float4 hi = g_thi[b * NTILE + t];
        const float dx = fmaxf(fmaxf(lo.x - qx, qx - hi.x), 0.0f);
        const float dy = fmaxf(fmaxf(lo.y - qy, qy - hi.y), 0.0f);
        const float dz = fmaxf(fmaxf(lo.z - qz, qz - hi.z), 0.0f);
        const float bd2 = fmaf(dx, dx, fmaf(dy, dy, dz * dz));
        // d^2(q, any point in tile) >= bd2. Skip iff bd2 >= ra + 2*mn.
        const bool canskip = (0.5f * (bd2 - ra) >= mn);
        if (__all_sync(0xffffffffu, canskip)) continue;
        const float4* __restrict__ tp = so + t * TPTS;
#pragma unroll 4
        for (int j = 0; j < TPTS; j++) {
            const float4 o = __ldg(tp + j);
            const float v = fmaf(nqx, o.x, fmaf(nqy, o.y, fmaf(nqz, o.z, o.w)));
            mn = fminf(mn, v);
        }
    }
    g_res[b * NPTS + orig] = fmaf(2.0f, mn, ra);
}

// ---------------------------------------------------------------- reduce
// One block, fixed strided assignment + fixed tree: bit-deterministic.
__global__ void k_reduce(const float* __restrict__ weights, float* __restrict__ out) {
    __shared__ float s[1024];
    int t = threadIdx.x;
    float sum = 0.0f;
    for (int i = t; i < TOTAL; i += 1024)
        sum += g_res[i] * __ldg(&weights[i >> 13]);
    s[t] = sum;
    __syncthreads();
    for (int d = 512; d > 0; d >>= 1) {
        if (t < d) s[t] += s[t + d];
        __syncthreads();
    }
    if (t == 0) out[0] = s[0] * (1.0f / (float)TOTAL);
}

extern "C" void kernel_launch(void* const* d_in, const int* in_sizes, int n_in,
                              void* d_out, int out_size) {
    const float* adv     = (const float*)d_in[0];  // adv_pc  [B, N, 3]  (queries)
    const float* ori     = (const float*)d_in[1];  // ori_pc  [B, N, 3]  (targets)
    const float* weights = (const float*)d_in[2];  // weights [B]
    float* out = (float*)d_out;                    // scalar

    k_zero   <<<256, 256>>>();
    k_count  <<<512, 256>>>(ori, adv);
    k_scan   <<<16, 1024>>>();
    k_scatter<<<512, 256>>>(ori, adv);
    k_aabb   <<<BATCH * NTILE / 8, 256>>>();
    k_query  <<<TOTAL / 128, 128>>>(0);
    k_reduce <<<1, 1024>>>(weights, out);
}

// round 13
// speedup vs baseline: 1.2336x; 1.2336x over previous
#include <cuda_runtime.h>
#include <math.h>

// Problem constants (fixed by the reference: B=8, N=8192, D=3)
#define BATCH   8
#define NPTS    8192
#define TOTAL   (BATCH * NPTS)        // 65536
#define G       32                    // cells per axis
#define NC      (G * G * G)           // 32768 cells per batch (2^15)
#define GRID_LO (-4.5f)
#define CELL_H  (0.28125f)            // 9.0 / 32
#define INV_H   (1.0f / CELL_H)
#define F_INF   __int_as_float(0x7f800000)
#define TPTS    128                   // ori points per tile
#define NTILE   (NPTS / TPTS)         // 64 tiles per batch
#define QPB     128                   // queries per block
#define QBLKS   (TOTAL / QPB)         // 512 query blocks

// Static scratch (no device allocation allowed).
__device__ int    g_cnt_ori[BATCH * NC];
__device__ int    g_off_ori[BATCH * NC];
__device__ int    g_cur_ori[BATCH * NC];
__device__ int    g_cnt_adv[BATCH * NC];
__device__ int    g_off_adv[BATCH * NC];
__device__ int    g_cur_adv[BATCH * NC];
__device__ float4 g_sorted_ori[TOTAL];   // (x, y, z, 0.5*||o||^2), Morton order
__device__ float4 g_sorted_adv[TOTAL];   // (x, y, z, ||a||^2),    Morton order
__device__ int    g_adv_orig[TOTAL];     // original index within batch
__device__ float4 g_tlo[BATCH * NTILE];  // tile AABB lows
__device__ float4 g_thi[BATCH * NTILE];  // tile AABB highs
__device__ float  g_res[TOTAL];          // per-query nearest dist^2, original order

__device__ __forceinline__ int cell1(float v) {
    int c = (int)floorf((v - GRID_LO) * INV_H);
    return min(G - 1, max(0, c));
}
__device__ __forceinline__ unsigned spread3(unsigned x) {
    x &= 0x3FF;
    x = (x | (x << 16)) & 0x030000FF;
    x = (x | (x << 8))  & 0x0300F00F;
    x = (x | (x << 4))  & 0x030C30C3;
    x = (x | (x << 2))  & 0x09249249;
    return x;
}
__device__ __forceinline__ int morton3(int cx, int cy, int cz) {
    return (int)(spread3(cx) | (spread3(cy) << 1) | (spread3(cz) << 2));
}

// ---------------------------------------------------------------- zero
__global__ void k_zero() {
    int i = blockIdx.x * blockDim.x + threadIdx.x;
    int stride = gridDim.x * blockDim.x;
    for (; i < BATCH * NC; i += stride) { g_cnt_ori[i] = 0; g_cnt_adv[i] = 0; }
}

// ---------------------------------------------------------------- count (Morton bins)
__global__ void k_count(const float* __restrict__ ori, const float* __restrict__ adv) {
    int t = blockIdx.x * blockDim.x + threadIdx.x;
    bool is_ori = t < TOTAL;
    int idx = is_ori ? t : t - TOTAL;
    int b = idx >> 13, i = idx & (NPTS - 1);
    const float* p = (is_ori ? ori : adv) + ((size_t)b * NPTS + i) * 3;
    int mc = morton3(cell1(p[0]), cell1(p[1]), cell1(p[2]));
    atomicAdd((is_ori ? g_cnt_ori : g_cnt_adv) + b * NC + mc, 1);
}

// ---------------------------------------------------------------- scan (batch-local offsets)
__global__ void k_scan() {
    __shared__ int s[1024];
    int kind = blockIdx.x >> 3, b = blockIdx.x & 7, t = threadIdx.x;
    int* cnt = (kind ? g_cnt_adv : g_cnt_ori) + b * NC;
    int* off = (kind ? g_off_adv : g_off_ori) + b * NC;
    int* cur = (kind ? g_cur_adv : g_cur_ori) + b * NC;
    const int CH = NC / 1024;   // 32
    int base = t * CH;
    int local = 0;
#pragma unroll
    for (int j = 0; j < CH; j++) local += cnt[base + j];
    s[t] = local;
    __syncthreads();
    for (int d = 1; d < 1024; d <<= 1) {
        int v = (t >= d) ? s[t - d] : 0;
        __syncthreads();
        s[t] += v;
        __syncthreads();
    }
    int run = s[t] - local;
    for (int j = 0; j < CH; j++) {
        off[base + j] = run;
        cur[base + j] = run;
        run += cnt[base + j];
    }
}

// ---------------------------------------------------------------- scatter (Morton order)
__global__ void k_scatter(const float* __restrict__ ori, const float* __restrict__ adv) {
    int t = blockIdx.x * blockDim.x + threadIdx.x;
    bool is_ori = t < TOTAL;
    int idx = is_ori ? t : t - TOTAL;
    int b = idx >> 13, i = idx & (NPTS - 1);
    const float* p = (is_ori ? ori : adv) + ((size_t)b * NPTS + i) * 3;
    float x = p[0], y = p[1], z = p[2];
    int mc = morton3(cell1(x), cell1(y), cell1(z));
    if (is_ori) {
        int pos = atomicAdd(&g_cur_ori[b * NC + mc], 1);
        g_sorted_ori[b * NPTS + pos] = make_float4(x, y, z, 0.5f * (x * x + y * y + z * z));
    } else {
        int pos = atomicAdd(&g_cur_adv[b * NC + mc], 1);
        g_sorted_adv[b * NPTS + pos] = make_float4(x, y, z, x * x + y * y + z * z);
        g_adv_orig[b * NPTS + pos] = i;
    }
}

// ---------------------------------------------------------------- tile AABBs (warp per tile)
__global__ __launch_bounds__(256) void k_aabb() {
    const int tglob = blockIdx.x * 8 + (threadIdx.x >> 5);  // 0..511
    const int lane = threadIdx.x & 31;
    float lx = F_INF, ly = F_INF, lz = F_INF;
    float hx = -F_INF, hy = -F_INF, hz = -F_INF;
#pragma unroll
    for (int k = 0; k < 4; k++) {
        float4 p = g_sorted_ori[tglob * TPTS + k * 32 + lane];
        lx = fminf(lx, p.x); ly = fminf(ly, p.y); lz = fminf(lz, p.z);
        hx = fmaxf(hx, p.x); hy = fmaxf(hy, p.y); hz = fmaxf(hz, p.z);
    }
#pragma unroll
    for (int s = 16; s > 0; s >>= 1) {
        lx = fminf(lx, __shfl_xor_sync(0xffffffffu, lx, s));
        ly = fminf(ly, __shfl_xor_sync(0xffffffffu, ly, s));
        lz = fminf(lz, __shfl_xor_sync(0xffffffffu, lz, s));
        hx = fmaxf(hx, __shfl_xor_sync(0xffffffffu, hx, s));
        hy = fmaxf(hy, __shfl_xor_sync(0xffffffffu, hy, s));
        hz = fmaxf(hz, __shfl_xor_sync(0xffffffffu, hz, s));
    }
    if (lane == 0) {
        g_tlo[tglob] = make_float4(lx, ly, lz, 0.f);
        g_thi[tglob] = make_float4(hx, hy, hz, 0.f);
    }
}

// ---------------------------------------------------------------- query (block per 128 Morton-contiguous queries)
__global__ __launch_bounds__(QPB) void k_query() {
    __shared__ __align__(16) float4 s_pts[TPTS];   // staged ori tile (2 KB)
    __shared__ float4 s_tlo[NTILE], s_thi[NTILE];  // tile AABBs (2 KB)
    __shared__ float s_key[NTILE];                 // block-box->tile-box dist^2
    __shared__ int   s_ord[NTILE];                 // tiles sorted by s_key asc
    __shared__ float s_red[QPB * 3];               // AABB reduction scratch
    __shared__ float s_blo[3], s_bhi[3];

    const int tid = threadIdx.x;
    const int slot = blockIdx.x * QPB + tid;       // blocks never straddle batches
    const int b = slot >> 13;
    const float4 q = g_sorted_adv[slot];
    const int orig = g_adv_orig[slot];
    const float qx = q.x, qy = q.y, qz = q.z, ra = q.w;
    const float nqx = -qx, nqy = -qy, nqz = -qz;
    const float4* __restrict__ so = g_sorted_ori + b * NPTS;

    // ---- block query AABB (min reduce on negated values for the max) ----
    s_red[tid] = qx; s_red[QPB + tid] = qy; s_red[2 * QPB + tid] = qz;
    __syncthreads();
    // mins
    for (int d = QPB / 2; d > 0; d >>= 1) {
        if (tid < d) {
            s_red[tid] = fminf(s_red[tid], s_red[tid + d]);
            s_red[QPB + tid] = fminf(s_red[QPB + tid], s_red[QPB + tid + d]);
            s_red[2 * QPB + tid] = fminf(s_red[2 * QPB + tid], s_red[2 * QPB + tid + d]);
        }
        __syncthreads();
    }
    if (tid == 0) { s_blo[0] = s_red[0]; s_blo[1] = s_red[QPB]; s_blo[2] = s_red[2 * QPB]; }
    __syncthreads();
    s_red[tid] = qx; s_red[QPB + tid] = qy; s_red[2 * QPB + tid] = qz;
    __syncthreads();
    for (int d = QPB / 2; d > 0; d >>= 1) {
        if (tid < d) {
            s_red[tid] = fmaxf(s_red[tid], s_red[tid + d]);
            s_red[QPB + tid] = fmaxf(s_red[QPB + tid], s_red[QPB + tid + d]);
            s_red[2 * QPB + tid] = fmaxf(s_red[2 * QPB + tid], s_red[2 * QPB + tid + d]);
        }
        __syncthreads();
    }
    if (tid == 0) { s_bhi[0] = s_red[0]; s_bhi[1] = s_red[QPB]; s_bhi[2] = s_red[2 * QPB]; }
    __syncthreads();

    // ---- per-tile block-level key + cache tile AABBs in smem ----
    if (tid < NTILE) {
        const float4 lo = g_tlo[b * NTILE + tid];
        const float4 hi = g_thi[b * NTILE + tid];
        s_tlo[tid] = lo; s_thi[tid] = hi;
        const float dx = fmaxf(fmaxf(lo.x - s_bhi[0], s_blo[0] - hi.x), 0.0f);
        const float dy = fmaxf(fmaxf(lo.y - s_bhi[1], s_blo[1] - hi.y), 0.0f);
        const float dz = fmaxf(fmaxf(lo.z - s_bhi[2], s_blo[2] - hi.z), 0.0f);
        s_key[tid] = fmaf(dx, dx, fmaf(dy, dy, dz * dz));
    }
    __syncthreads();
    if (tid < NTILE) {                 // deterministic rank sort (64x64)
        const float mykey = s_key[tid];
        int rank = 0;
#pragma unroll 8
        for (int u = 0; u < NTILE; u++) {
            const float ku = s_key[u];
            rank += (ku < mykey) || (ku == mykey && u < tid);
        }
        s_ord[rank] = tid;
    }
    __syncthreads();

    // ---- walk tiles ascending; vote, stage, eval (R1 inner loop) ----
    float m0 = F_INF, m1 = F_INF, m2 = F_INF, m3 = F_INF;
    for (int k = 0; k < NTILE; k++) {
        const int t = s_ord[k];
        const float4 lo = s_tlo[t], hi = s_thi[t];
        const float dx = fmaxf(fmaxf(lo.x - qx, qx - hi.x), 0.0f);
        const float dy = fmaxf(fmaxf(lo.y - qy, qy - hi.y), 0.0f);
        const float dz = fmaxf(fmaxf(lo.z - qz, qz - hi.z), 0.0f);
        const float bd2 = fmaf(dx, dx, fmaf(dy, dy, dz * dz));
        const float mn = fminf(fminf(m0, m1), fminf(m2, m3));
        // need this tile iff it could beat my current best: bd2 < ra + 2*mn
        const int need = !(0.5f * (bd2 - ra) >= mn);     // true when mn == +inf
        if (!__syncthreads_or(need)) continue;
        // stage tile (128 points, one per thread)
        s_pts[tid] = __ldg(so + t * TPTS + tid);
        __syncthreads();
#pragma unroll 4
        for (int j = 0; j < TPTS; j += 4) {
            const float4 o0 = s_pts[j],     o1 = s_pts[j + 1];
            const float4 o2 = s_pts[j + 2], o3 = s_pts[j + 3];
            m0 = fminf(m0, fmaf(nqx, o0.x, fmaf(nqy, o0.y, fmaf(nqz, o0.z, o0.w))));
            m1 = fminf(m1, fmaf(nqx, o1.x, fmaf(nqy, o1.y, fmaf(nqz, o1.z, o1.w))));
            m2 = fminf(m2, fmaf(nqx, o2.x, fmaf(nqy, o2.y, fmaf(nqz, o2.z, o2.w))));
            m3 = fminf(m3, fmaf(nqx, o3.x, fmaf(nqy, o3.y, fmaf(nqz, o3.z, o3.w))));
        }
        __syncthreads();
    }
    const float mn = fminf(fminf(m0, m1), fminf(m2, m3));
    g_res[b * NPTS + orig] = fmaf(2.0f, mn, ra);
}

// ---------------------------------------------------------------- reduce
__global__ void k_reduce(const float* __restrict__ weights, float* __restrict__ out) {
    __shared__ float s[1024];
    int t = threadIdx.x;
    float sum = 0.0f;
    for (int i = t; i < TOTAL; i += 1024)
        sum += g_res[i] * __ldg(&weights[i >> 13]);
    s[t] = sum;
    __syncthreads();
    for (int d = 512; d > 0; d >>= 1) {
        if (t < d) s[t] += s[t + d];
        __syncthreads();
    }
    if (t == 0) out[0] = s[0] * (1.0f / (float)TOTAL);
}

extern "C" void kernel_launch(void* const* d_in, const int* in_sizes, int n_in,
                              void* d_out, int out_size) {
    const float* adv     = (const float*)d_in[0];  // adv_pc  [B, N, 3]  (queries)
    const float* ori     = (const float*)d_in[1];  // ori_pc  [B, N, 3]  (targets)
    const float* weights = (const float*)d_in[2];  // weights [B]
    float* out = (float*)d_out;                    // scalar

    k_zero   <<<256, 256>>>();
    k_count  <<<512, 256>>>(ori, adv);
    k_scan   <<<16, 1024>>>();
    k_scatter<<<512, 256>>>(ori, adv);
    k_aabb   <<<BATCH * NTILE / 8, 256>>>();
    k_query  <<<QBLKS, QPB>>>();
    k_reduce <<<1, 1024>>>(weights, out);
}

// round 16
// speedup vs baseline: 2.7060x; 2.1936x over previous
#include <cuda_runtime.h>
#include <math.h>

// Problem constants (fixed by the reference: B=8, N=8192, D=3)
#define BATCH   8
#define NPTS    8192
#define TOTAL   (BATCH * NPTS)        // 65536
#define BG      16                    // Morton bin cells per axis (coarse)
#define BNC     (BG * BG * BG)        // 4096 bins per batch
#define GRID_LO (-4.5f)
#define BIN_H   (0.5625f)             // 9.0 / 16
#define BIN_INV (1.0f / BIN_H)
#define F_INF   __int_as_float(0x7f800000)
#define TPTS    128                   // ori points per tile
#define NTILE   (NPTS / TPTS)         // 64 tiles per batch
#define QTHREADS 128                  // query kernel threads per block
#define QPERBLK  256                  // queries per block (2 per thread)
#define QBLOCKS  (TOTAL / QPERBLK)    // 256 blocks (32 per batch)

// Static scratch (no device allocation allowed).
__device__ int    g_cnt_ori[BATCH * BNC];
__device__ int    g_off_ori[BATCH * BNC];
__device__ int    g_cur_ori[BATCH * BNC];
__device__ int    g_cnt_adv[BATCH * BNC];
__device__ int    g_off_adv[BATCH * BNC];
__device__ int    g_cur_adv[BATCH * BNC];
__device__ float4 g_sorted_ori[TOTAL];   // (x, y, z, 0.5*||o||^2), Morton order
__device__ float4 g_sorted_adv[TOTAL];   // (x, y, z, ||a||^2),    Morton order
__device__ int    g_adv_meta[TOTAL];     // (bin << 13) | orig-index-in-batch
__device__ float4 g_tlo[BATCH * NTILE];  // tile AABB lows
__device__ float4 g_thi[BATCH * NTILE];  // tile AABB highs
__device__ float  g_res[TOTAL];          // per-query nearest dist^2, original order

__device__ __forceinline__ int bin1(float v) {
    int c = (int)floorf((v - GRID_LO) * BIN_INV);
    return min(BG - 1, max(0, c));
}
__device__ __forceinline__ unsigned spread3(unsigned x) {
    x &= 0x3FF;
    x = (x | (x << 16)) & 0x030000FF;
    x = (x | (x << 8))  & 0x0300F00F;
    x = (x | (x << 4))  & 0x030C30C3;
    x = (x | (x << 2))  & 0x09249249;
    return x;
}
__device__ __forceinline__ int morton3(int cx, int cy, int cz) {
    return (int)(spread3(cx) | (spread3(cy) << 1) | (spread3(cz) << 2));
}

// ---------------------------------------------------------------- zero
__global__ void k_zero() {
    int i = blockIdx.x * blockDim.x + threadIdx.x;
    if (i < BATCH * BNC) { g_cnt_ori[i] = 0; g_cnt_adv[i] = 0; }
}

// ---------------------------------------------------------------- count (Morton bins)
__global__ void k_count(const float* __restrict__ ori, const float* __restrict__ adv) {
    int t = blockIdx.x * blockDim.x + threadIdx.x;
    bool is_ori = t < TOTAL;
    int idx = is_ori ? t : t - TOTAL;
    int b = idx >> 13, i = idx & (NPTS - 1);
    const float* p = (is_ori ? ori : adv) + ((size_t)b * NPTS + i) * 3;
    int mc = morton3(bin1(p[0]), bin1(p[1]), bin1(p[2]));
    atomicAdd((is_ori ? g_cnt_ori : g_cnt_adv) + b * BNC + mc, 1);
}

// ---------------------------------------------------------------- scan (batch-local offsets)
// Blocks 0..7: ori batches. Blocks 8..15: adv batches. 1024 threads, CH=4.
__global__ void k_scan() {
    __shared__ int s[1024];
    int kind = blockIdx.x >> 3, b = blockIdx.x & 7, t = threadIdx.x;
    int* cnt = (kind ? g_cnt_adv : g_cnt_ori) + b * BNC;
    int* off = (kind ? g_off_adv : g_off_ori) + b * BNC;
    int* cur = (kind ? g_cur_adv : g_cur_ori) + b * BNC;
    const int CH = BNC / 1024;   // 4
    int base = t * CH;
    int local = 0;
#pragma unroll
    for (int j = 0; j < CH; j++) local += cnt[base + j];
    s[t] = local;
    __syncthreads();
    for (int d = 1; d < 1024; d <<= 1) {
        int v = (t >= d) ? s[t - d] : 0;
        __syncthreads();
        s[t] += v;
        __syncthreads();
    }
    int run = s[t] - local;
#pragma unroll
    for (int j = 0; j < CH; j++) {
        off[base + j] = run;
        cur[base + j] = run;
        run += cnt[base + j];
    }
}

// ---------------------------------------------------------------- scatter (Morton order)
__global__ void k_scatter(const float* __restrict__ ori, const float* __restrict__ adv) {
    int t = blockIdx.x * blockDim.x + threadIdx.x;
    bool is_ori = t < TOTAL;
    int idx = is_ori ? t : t - TOTAL;
    int b = idx >> 13, i = idx & (NPTS - 1);
    const float* p = (is_ori ? ori : adv) + ((size_t)b * NPTS + i) * 3;
    float x = p[0], y = p[1], z = p[2];
    int mc = morton3(bin1(x), bin1(y), bin1(z));
    if (is_ori) {
        int pos = atomicAdd(&g_cur_ori[b * BNC + mc], 1);   // batch-local
        g_sorted_ori[b * NPTS + pos] = make_float4(x, y, z, 0.5f * (x * x + y * y + z * z));
    } else {
        int pos = atomicAdd(&g_cur_adv[b * BNC + mc], 1);
        g_sorted_adv[b * NPTS + pos] = make_float4(x, y, z, x * x + y * y + z * z);
        g_adv_meta[b * NPTS + pos] = (mc << 13) | i;
    }
}

// ---------------------------------------------------------------- tile AABBs (warp per tile, 512 tiles)
__global__ __launch_bounds__(256) void k_aabb() {
    const int tglob = blockIdx.x * 8 + (threadIdx.x >> 5);  // 0..511
    const int lane = threadIdx.x & 31;
    float lx = F_INF, ly = F_INF, lz = F_INF;
    float hx = -F_INF, hy = -F_INF, hz = -F_INF;
#pragma unroll
    for (int k = 0; k < 4; k++) {
        float4 p = g_sorted_ori[tglob * TPTS + k * 32 + lane];
        lx = fminf(lx, p.x); ly = fminf(ly, p.y); lz = fminf(lz, p.z);
        hx = fmaxf(hx, p.x); hy = fmaxf(hy, p.y); hz = fmaxf(hz, p.z);
    }
#pragma unroll
    for (int s = 16; s > 0; s >>= 1) {
        lx = fminf(lx, __shfl_xor_sync(0xffffffffu, lx, s));
        ly = fminf(ly, __shfl_xor_sync(0xffffffffu, ly, s));
        lz = fminf(lz, __shfl_xor_sync(0xffffffffu, lz, s));
        hx = fmaxf(hx, __shfl_xor_sync(0xffffffffu, hx, s));
        hy = fmaxf(hy, __shfl_xor_sync(0xffffffffu, hy, s));
        hz = fmaxf(hz, __shfl_xor_sync(0xffffffffu, hz, s));
    }
    if (lane == 0) {
        g_tlo[tglob] = make_float4(lx, ly, lz, 0.f);
        g_thi[tglob] = make_float4(hx, hy, hz, 0.f);
    }
}

// ---------------------------------------------------------------- query
// R1 skeleton: 128 threads, 2 queries/thread, stage 1024 ori pts to smem,
// broadcast-LDS inner loop. Added: warp owns 64 Morton-contiguous queries;
// per-warp home-tile seed; per-128-pt-subtile AABB skip vote (__all_sync).
__global__ __launch_bounds__(QTHREADS) void k_query() {
    __shared__ __align__(16) float4 s_tile[1024];        // 16 KB
    __shared__ float4 s_lo[NTILE], s_hi[NTILE];          // 2 KB

    const int tid = threadIdx.x;
    const int wid = tid >> 5, lane = tid & 31;
    const int b = blockIdx.x >> 5;                       // 32 blocks per batch
    const int qbase = (blockIdx.x & 31) * QPERBLK;
    const float4* __restrict__ so = g_sorted_ori + b * NPTS;
    const float4* __restrict__ sa = g_sorted_adv + b * NPTS;

    // Load tile AABBs to smem.
    if (tid < NTILE) { s_lo[tid] = g_tlo[b * NTILE + tid]; s_hi[tid] = g_thi[b * NTILE + tid]; }

    // My two adjacent sorted queries: warp w owns [qbase+64w, +64).
    const int q0 = qbase + wid * 64 + lane * 2;
    const float4 qa = sa[q0], qb = sa[q0 + 1];
    const int meta0 = g_adv_meta[b * NPTS + q0];
    const int meta1 = g_adv_meta[b * NPTS + q0 + 1];
    const float nax = -qa.x, nay = -qa.y, naz = -qa.z, ra0 = qa.w;
    const float nbx = -qb.x, nby = -qb.y, nbz = -qb.z, ra1 = qb.w;
    float mn0 = F_INF, mn1 = F_INF;

    // Seed: evaluate the warp's (median lane's) home tile via uniform LDG.
    {
        int ht = min(g_off_ori[b * BNC + (meta0 >> 13)] >> 7, NTILE - 1);
        ht = __shfl_sync(0xffffffffu, ht, 16);
        const float4* __restrict__ tp = so + ht * TPTS;
#pragma unroll 4
        for (int j = 0; j < TPTS; j++) {
            const float4 o = __ldg(tp + j);
            mn0 = fminf(mn0, fmaf(nax, o.x, fmaf(nay, o.y, fmaf(naz, o.z, o.w))));
            mn1 = fminf(mn1, fmaf(nbx, o.x, fmaf(nby, o.y, fmaf(nbz, o.z, o.w))));
        }
    }
    __syncthreads();   // AABBs staged

    for (int t0 = 0; t0 < NPTS; t0 += 1024) {
        // Stage 1024 ori points (8 independent loads/thread).
        for (int i = tid; i < 1024; i += QTHREADS)
            s_tile[i] = __ldg(so + t0 + i);
        __syncthreads();

#pragma unroll
        for (int sub = 0; sub < 8; sub++) {
            const int gt = (t0 >> 7) + sub;
            const float4 lo = s_lo[gt], hi = s_hi[gt];
            // Exact lower bound of d^2 from each query to any point in tile.
            float dx = fmaxf(fmaxf(lo.x - qa.x, qa.x - hi.x), 0.0f);
            float dy = fmaxf(fmaxf(lo.y - qa.y, qa.y - hi.y), 0.0f);
            float dz = fmaxf(fmaxf(lo.z - qa.z, qa.z - hi.z), 0.0f);
            const float bdA = fmaf(dx, dx, fmaf(dy, dy, dz * dz));
            dx = fmaxf(fmaxf(lo.x - qb.x, qb.x - hi.x), 0.0f);
            dy = fmaxf(fmaxf(lo.y - qb.y, qb.y - hi.y), 0.0f);
            dz = fmaxf(fmaxf(lo.z - qb.z, qb.z - hi.z), 0.0f);
            const float bdB = fmaf(dx, dx, fmaf(dy, dy, dz * dz));
            // skip iff bd >= current best d^2 (= ra + 2*mn); inf-safe.
            const bool skip = (bdA >= fmaf(2.0f, mn0, ra0)) &&
                              (bdB >= fmaf(2.0f, mn1, ra1));
            if (__all_sync(0xffffffffu, skip)) continue;

            const float4* __restrict__ sp = s_tile + sub * TPTS;
#pragma unroll 8
            for (int j = 0; j < TPTS; j++) {
                const float4 o = sp[j];   // broadcast LDS.128
                mn0 = fminf(mn0, fmaf(nax, o.x, fmaf(nay, o.y, fmaf(naz, o.z, o.w))));
                mn1 = fminf(mn1, fmaf(nbx, o.x, fmaf(nby, o.y, fmaf(nbz, o.z, o.w))));
            }
        }
        __syncthreads();
    }

    g_res[b * NPTS + (meta0 & (NPTS - 1))] = fmaf(2.0f, mn0, ra0);
    g_res[b * NPTS + (meta1 & (NPTS - 1))] = fmaf(2.0f, mn1, ra1);
}

// ---------------------------------------------------------------- reduce
// One block, fixed strided assignment + fixed tree: bit-deterministic.
__global__ void k_reduce(const float* __restrict__ weights, float* __restrict__ out) {
    __shared__ float s[1024];
    int t = threadIdx.x;
    float sum = 0.0f;
    for (int i = t; i < TOTAL; i += 1024)
        sum += g_res[i] * __ldg(&weights[i >> 13]);
    s[t] = sum;
    __syncthreads();
    for (int d = 512; d > 0; d >>= 1) {
        if (t < d) s[t] += s[t + d];
        __syncthreads();
    }
    if (t == 0) out[0] = s[0] * (1.0f / (float)TOTAL);
}

extern "C" void kernel_launch(void* const* d_in, const int* in_sizes, int n_in,
                              void* d_out, int out_size) {
    const float* adv     = (const float*)d_in[0];  // adv_pc  [B, N, 3]  (queries)
    const float* ori     = (const float*)d_in[1];  // ori_pc  [B, N, 3]  (targets)
    const float* weights = (const float*)d_in[2];  // weights [B]
    float* out = (float*)d_out;                    // scalar

    k_zero   <<<(BATCH * BNC + 255) / 256, 256>>>();
    k_count  <<<512, 256>>>(ori, adv);
    k_scan   <<<16, 1024>>>();
    k_scatter<<<512, 256>>>(ori, adv);
    k_aabb   <<<BATCH * NTILE / 8, 256>>>();
    k_query  <<<QBLOCKS, QTHREADS>>>();
    k_reduce <<<1, 1024>>>(weights, out);
}